// round 1
// baseline (speedup 1.0000x reference)
#include <cuda_runtime.h>
#include <cstdint>

#define NATOMS   4096
#define BLOCK_SZ 512
#define BOXF     44.0f
#define INV_BOX  (1.0f / 44.0f)
#define CUT2     (17.5f * 17.5f)
#define TPB      256

// per-CTA energy partials (deterministic two-stage reduction, no float atomics)
__device__ float g_epart[NATOMS];

__inline__ __device__ float warp_sum(float v) {
    #pragma unroll
    for (int o = 16; o > 0; o >>= 1) v += __shfl_down_sync(0xffffffffu, v, o);
    return v;
}

__global__ __launch_bounds__(TPB)
void bmh_pair_kernel(const float* __restrict__ coords,
                     const float* __restrict__ A,
                     const float* __restrict__ C,
                     const float* __restrict__ D,
                     const float* __restrict__ RHO,
                     const float* __restrict__ SIG,
                     float* __restrict__ out)
{
    const int i   = blockIdx.x;
    const int tid = threadIdx.x;

    const float xi = __ldg(&coords[3 * i + 0]);
    const float yi = __ldg(&coords[3 * i + 1]);
    const float zi = __ldg(&coords[3 * i + 2]);

    const int  loci = i & (BLOCK_SZ - 1);
    const int  blki = i >> 9;
    const size_t row = (size_t)i * NATOMS;

    const float* __restrict__ Ar = A   + row;
    const float* __restrict__ Cr = C   + row;
    const float* __restrict__ Dr = D   + row;
    const float* __restrict__ Rr = RHO + row;
    const float* __restrict__ Sr = SIG + row;

    float fx = 0.f, fy = 0.f, fz = 0.f, en = 0.f;

    #pragma unroll 4
    for (int j = tid; j < NATOMS; j += TPB) {
        float dx = xi - __ldg(&coords[3 * j + 0]);
        float dy = yi - __ldg(&coords[3 * j + 1]);
        float dz = zi - __ldg(&coords[3 * j + 2]);
        // minimum image
        dx -= rintf(dx * INV_BOX) * BOXF;
        dy -= rintf(dy * INV_BOX) * BOXF;
        dz -= rintf(dz * INV_BOX) * BOXF;
        const float r2 = fmaf(dx, dx, fmaf(dy, dy, dz * dz));

        const bool valid = (r2 < CUT2) && ((j & (BLOCK_SZ - 1)) != loci);
        if (valid) {
            const float w = ((j >> 9) == blki) ? 1.0f : 2.0f;

            const float a   = __ldg(Ar + j);
            const float c   = __ldg(Cr + j);
            const float dd  = __ldg(Dr + j);
            const float rh  = __ldg(Rr + j);
            const float sg  = __ldg(Sr + j);

            const float r2c  = fmaxf(r2, 1.0f);       // clamp(min=1) on squared dist
            const float dinv = rsqrtf(r2c);
            const float d    = r2c * dinv;            // sqrt(r2c)

            const float invrh = __fdividef(1.0f, rh);
            const float e     = __expf((sg - d) * invrh);

            const float inv2 = dinv * dinv;
            const float inv6 = inv2 * inv2 * inv2;
            const float inv8 = inv6 * inv2;

            const float ae = a * e;
            const float pe = ae - c * inv6 + dd * inv8;
            en = fmaf(0.5f * w, pe, en);

            // force only when the clamp is inactive (grad of max(r2,1) is 0 below 1)
            if (r2 > 1.0f) {
                // g = pe'(d)/d = -a*e/(rho*d) + 6*c/d^8 - 8*dd/d^10
                float g = fmaf(6.0f * c, inv8,
                               fmaf(-8.0f * dd, inv8 * inv2,
                                    -(ae * invrh) * dinv));
                g *= w;
                fx = fmaf(g, dx, fx);
                fy = fmaf(g, dy, fy);
                fz = fmaf(g, dz, fz);
            }
        }
    }

    // ---- deterministic block reduction (fixed shuffle tree) ----
    fx = warp_sum(fx); fy = warp_sum(fy); fz = warp_sum(fz); en = warp_sum(en);

    __shared__ float sm[4][TPB / 32];
    const int lane = tid & 31, wid = tid >> 5;
    if (lane == 0) { sm[0][wid] = fx; sm[1][wid] = fy; sm[2][wid] = fz; sm[3][wid] = en; }
    __syncthreads();

    if (wid == 0) {
        const int nw = TPB / 32;
        float vfx = (lane < nw) ? sm[0][lane] : 0.f;
        float vfy = (lane < nw) ? sm[1][lane] : 0.f;
        float vfz = (lane < nw) ? sm[2][lane] : 0.f;
        float ven = (lane < nw) ? sm[3][lane] : 0.f;
        vfx = warp_sum(vfx); vfy = warp_sum(vfy); vfz = warp_sum(vfz); ven = warp_sum(ven);
        if (lane == 0) {
            out[1 + 3 * i + 0] = vfx;
            out[1 + 3 * i + 1] = vfy;
            out[1 + 3 * i + 2] = vfz;
            g_epart[i] = ven;
        }
    }
}

__global__ __launch_bounds__(TPB)
void bmh_energy_reduce(float* __restrict__ out)
{
    // single block; fixed-order strided accumulation in double, then fixed tree
    double s = 0.0;
    for (int k = threadIdx.x; k < NATOMS; k += TPB) s += (double)g_epart[k];

    __shared__ double sd[TPB];
    sd[threadIdx.x] = s;
    __syncthreads();
    #pragma unroll
    for (int o = TPB / 2; o > 0; o >>= 1) {
        if (threadIdx.x < o) sd[threadIdx.x] += sd[threadIdx.x + o];
        __syncthreads();
    }
    if (threadIdx.x == 0) out[0] = (float)sd[0];
}

extern "C" void kernel_launch(void* const* d_in, const int* in_sizes, int n_in,
                              void* d_out, int out_size)
{
    const float* coords = (const float*)d_in[0];
    // d_in[1] = q (unused by the energy; reproduced faithfully)
    const float* A   = (const float*)d_in[2];
    const float* C   = (const float*)d_in[3];
    const float* D   = (const float*)d_in[4];
    const float* RHO = (const float*)d_in[5];
    const float* SIG = (const float*)d_in[6];
    float* out = (float*)d_out;

    bmh_pair_kernel<<<NATOMS, TPB>>>(coords, A, C, D, RHO, SIG, out);
    bmh_energy_reduce<<<1, TPB>>>(out);
}

// round 2
// speedup vs baseline: 1.3774x; 1.3774x over previous
#include <cuda_runtime.h>
#include <cstdint>

#define NATOMS   4096
#define BLOCK_SZ 512
#define BOXF     44.0f
#define INV_BOX  (1.0f / 44.0f)
#define CUT2     (17.5f * 17.5f)
#define TPB      256
#define NITER    (NATOMS / TPB)   // 16

// per-CTA energy partials + completion counter (deterministic last-block reduce)
__device__ float        g_epart[NATOMS];
__device__ unsigned int g_done;   // zero-initialized; reset by last block each launch

__inline__ __device__ float warp_sum(float v) {
    #pragma unroll
    for (int o = 16; o > 0; o >>= 1) v += __shfl_down_sync(0xffffffffu, v, o);
    return v;
}

__global__ __launch_bounds__(TPB)
void bmh_pair_kernel(const float* __restrict__ coords,
                     const float* __restrict__ A,
                     const float* __restrict__ C,
                     const float* __restrict__ D,
                     const float* __restrict__ RHO,
                     const float* __restrict__ SIG,
                     float* __restrict__ out)
{
    const int i   = blockIdx.x;
    const int tid = threadIdx.x;

    const float xi = __ldg(&coords[3 * i + 0]);
    const float yi = __ldg(&coords[3 * i + 1]);
    const float zi = __ldg(&coords[3 * i + 2]);

    const int loci = i & (BLOCK_SZ - 1);
    const int blki = i >> 9;
    const size_t row = (size_t)i * NATOMS;

    const float* __restrict__ Ar = A   + row;
    const float* __restrict__ Cr = C   + row;
    const float* __restrict__ Dr = D   + row;
    const float* __restrict__ Rr = RHO + row;
    const float* __restrict__ Sr = SIG + row;

    float fx = 0.f, fy = 0.f, fz = 0.f, en = 0.f;

    #pragma unroll 4
    for (int m = 0; m < NITER; ++m) {
        const int j = m * TPB + tid;

        // unconditional loads — hoisted out of any branch for max MLP
        const float a  = __ldg(Ar + j);
        const float c  = __ldg(Cr + j);
        const float dd = __ldg(Dr + j);
        const float rh = __ldg(Rr + j);
        const float sg = __ldg(Sr + j);
        const float xj = __ldg(&coords[3 * j + 0]);
        const float yj = __ldg(&coords[3 * j + 1]);
        const float zj = __ldg(&coords[3 * j + 2]);

        float dx = xi - xj, dy = yi - yj, dz = zi - zj;
        dx -= rintf(dx * INV_BOX) * BOXF;
        dy -= rintf(dy * INV_BOX) * BOXF;
        dz -= rintf(dz * INV_BOX) * BOXF;
        const float r2 = fmaf(dx, dx, fmaf(dy, dy, dz * dz));

        const bool  valid = (r2 < CUT2) && ((j & (BLOCK_SZ - 1)) != loci);
        const float wbase = ((j >> 9) == blki) ? 1.0f : 2.0f;
        const float wsel  = valid ? wbase : 0.0f;              // energy weight
        const float wfrc  = (valid && r2 > 1.0f) ? wbase : 0.0f; // force weight (clamp grad)

        const float r2c  = fmaxf(r2, 1.0f);
        const float dinv = rsqrtf(r2c);
        const float d    = r2c * dinv;

        const float invrh = __fdividef(1.0f, rh);
        const float e     = __expf((sg - d) * invrh);

        const float inv2 = dinv * dinv;
        const float inv6 = inv2 * inv2 * inv2;
        const float inv8 = inv6 * inv2;

        const float ae = a * e;
        const float pe = fmaf(dd, inv8, fmaf(-c, inv6, ae));
        en = fmaf(0.5f * wsel, pe, en);

        // g = pe'(d)/d = -a*e/(rho*d) + 6*c/d^8 - 8*dd/d^10
        float g = fmaf(6.0f * c, inv8,
                       fmaf(-8.0f * dd, inv8 * inv2,
                            -(ae * invrh) * dinv));
        g *= wfrc;
        fx = fmaf(g, dx, fx);
        fy = fmaf(g, dy, fy);
        fz = fmaf(g, dz, fz);
    }

    // ---- deterministic block reduction (fixed shuffle tree) ----
    fx = warp_sum(fx); fy = warp_sum(fy); fz = warp_sum(fz); en = warp_sum(en);

    __shared__ float sm[4][TPB / 32];
    const int lane = tid & 31, wid = tid >> 5;
    if (lane == 0) { sm[0][wid] = fx; sm[1][wid] = fy; sm[2][wid] = fz; sm[3][wid] = en; }
    __syncthreads();

    if (wid == 0) {
        const int nw = TPB / 32;
        float vfx = (lane < nw) ? sm[0][lane] : 0.f;
        float vfy = (lane < nw) ? sm[1][lane] : 0.f;
        float vfz = (lane < nw) ? sm[2][lane] : 0.f;
        float ven = (lane < nw) ? sm[3][lane] : 0.f;
        vfx = warp_sum(vfx); vfy = warp_sum(vfy); vfz = warp_sum(vfz); ven = warp_sum(ven);
        if (lane == 0) {
            out[1 + 3 * i + 0] = vfx;
            out[1 + 3 * i + 1] = vfy;
            out[1 + 3 * i + 2] = vfz;
            g_epart[i] = ven;
        }
    }

    // ---- last-block deterministic energy reduction (no 2nd kernel) ----
    __shared__ int amLast;
    if (tid == 0) {
        __threadfence();
        amLast = (atomicAdd(&g_done, 1u) == (unsigned)(gridDim.x - 1));
    }
    __syncthreads();

    if (amLast) {
        double s = 0.0;
        #pragma unroll
        for (int k = tid; k < NATOMS; k += TPB) s += (double)g_epart[k];

        __shared__ double sd[TPB];
        sd[tid] = s;
        __syncthreads();
        #pragma unroll
        for (int o = TPB / 2; o > 0; o >>= 1) {
            if (tid < o) sd[tid] += sd[tid + o];
            __syncthreads();
        }
        if (tid == 0) {
            out[0] = (float)sd[0];
            g_done = 0;   // reset for next graph replay
        }
    }
}

extern "C" void kernel_launch(void* const* d_in, const int* in_sizes, int n_in,
                              void* d_out, int out_size)
{
    const float* coords = (const float*)d_in[0];
    // d_in[1] = q (computed-but-unused upstream; faithfully ignored)
    const float* A   = (const float*)d_in[2];
    const float* C   = (const float*)d_in[3];
    const float* D   = (const float*)d_in[4];
    const float* RHO = (const float*)d_in[5];
    const float* SIG = (const float*)d_in[6];
    float* out = (float*)d_out;

    bmh_pair_kernel<<<NATOMS, TPB>>>(coords, A, C, D, RHO, SIG, out);
}

// round 3
// speedup vs baseline: 1.6749x; 1.2161x over previous
#include <cuda_runtime.h>
#include <cstdint>

#define NATOMS   4096
#define BLOCK_SZ 512
#define BOXF     44.0f
#define INV_BOX  (1.0f / 44.0f)
#define CUT2     (17.5f * 17.5f)
#define TPB      256
#define NITER    (NATOMS / (TPB * 4))   // 4 quads per thread

// per-CTA energy partials + completion counter (deterministic last-block reduce)
__device__ float        g_epart[NATOMS];
__device__ unsigned int g_done;   // zero-init; reset by last block each launch

__inline__ __device__ float warp_sum(float v) {
    #pragma unroll
    for (int o = 16; o > 0; o >>= 1) v += __shfl_down_sync(0xffffffffu, v, o);
    return v;
}

// one pair's math; accumulates energy + force
__inline__ __device__ void pair_math(float dx, float dy, float dz,
                                     float a, float c, float dd, float rh, float sg,
                                     bool locok, float wbase,
                                     float& fx, float& fy, float& fz, float& en)
{
    dx -= rintf(dx * INV_BOX) * BOXF;
    dy -= rintf(dy * INV_BOX) * BOXF;
    dz -= rintf(dz * INV_BOX) * BOXF;
    const float r2 = fmaf(dx, dx, fmaf(dy, dy, dz * dz));

    const bool  valid = (r2 < CUT2) && locok;
    const float wsel  = valid ? wbase : 0.0f;
    const float wfrc  = (valid && r2 > 1.0f) ? wbase : 0.0f;

    const float r2c  = fmaxf(r2, 1.0f);
    const float dinv = rsqrtf(r2c);
    const float d    = r2c * dinv;

    const float invrh = __fdividef(1.0f, rh);
    const float e     = __expf((sg - d) * invrh);

    const float inv2 = dinv * dinv;
    const float inv6 = inv2 * inv2 * inv2;
    const float inv8 = inv6 * inv2;

    const float ae = a * e;
    const float pe = fmaf(dd, inv8, fmaf(-c, inv6, ae));
    en = fmaf(0.5f * wsel, pe, en);

    float g = fmaf(6.0f * c, inv8,
                   fmaf(-8.0f * dd, inv8 * inv2,
                        -(ae * invrh) * dinv));
    g *= wfrc;
    fx = fmaf(g, dx, fx);
    fy = fmaf(g, dy, fy);
    fz = fmaf(g, dz, fz);
}

__global__ __launch_bounds__(TPB)
void bmh_pair_kernel(const float* __restrict__ coords,
                     const float* __restrict__ A,
                     const float* __restrict__ C,
                     const float* __restrict__ D,
                     const float* __restrict__ RHO,
                     const float* __restrict__ SIG,
                     float* __restrict__ out)
{
    const int i   = blockIdx.x;
    const int tid = threadIdx.x;

    const float xi = __ldg(&coords[3 * i + 0]);
    const float yi = __ldg(&coords[3 * i + 1]);
    const float zi = __ldg(&coords[3 * i + 2]);

    const int loci = i & (BLOCK_SZ - 1);
    const int blki = i >> 9;
    const size_t row = (size_t)i * NATOMS;

    const float4* __restrict__ Ar = (const float4*)(A   + row);
    const float4* __restrict__ Cr = (const float4*)(C   + row);
    const float4* __restrict__ Dr = (const float4*)(D   + row);
    const float4* __restrict__ Rr = (const float4*)(RHO + row);
    const float4* __restrict__ Sr = (const float4*)(SIG + row);
    const float4* __restrict__ cf = (const float4*)coords;

    float fx = 0.f, fy = 0.f, fz = 0.f, en = 0.f;

    #pragma unroll 2
    for (int m = 0; m < NITER; ++m) {
        const int jv = m * TPB + tid;   // quad index
        const int j0 = jv * 4;

        // 128-bit loads: 5 params + 3 coord vectors per 4 pairs
        const float4 a4 = __ldg(Ar + jv);
        const float4 c4 = __ldg(Cr + jv);
        const float4 d4 = __ldg(Dr + jv);
        const float4 r4 = __ldg(Rr + jv);
        const float4 s4 = __ldg(Sr + jv);
        const float4 c0 = __ldg(cf + 3 * jv + 0);
        const float4 c1 = __ldg(cf + 3 * jv + 1);
        const float4 c2 = __ldg(cf + 3 * jv + 2);

        // one weight / block test per quad (512 % 4 == 0)
        const float wbase = ((j0 >> 9) == blki) ? 1.0f : 2.0f;
        const int   locj0 = j0 & (BLOCK_SZ - 1);

        pair_math(xi - c0.x, yi - c0.y, zi - c0.z,
                  a4.x, c4.x, d4.x, r4.x, s4.x,
                  (locj0 + 0) != loci, wbase, fx, fy, fz, en);
        pair_math(xi - c0.w, yi - c1.x, zi - c1.y,
                  a4.y, c4.y, d4.y, r4.y, s4.y,
                  (locj0 + 1) != loci, wbase, fx, fy, fz, en);
        pair_math(xi - c1.z, yi - c1.w, zi - c2.x,
                  a4.z, c4.z, d4.z, r4.z, s4.z,
                  (locj0 + 2) != loci, wbase, fx, fy, fz, en);
        pair_math(xi - c2.y, yi - c2.z, zi - c2.w,
                  a4.w, c4.w, d4.w, r4.w, s4.w,
                  (locj0 + 3) != loci, wbase, fx, fy, fz, en);
    }

    // ---- deterministic block reduction (fixed shuffle tree) ----
    fx = warp_sum(fx); fy = warp_sum(fy); fz = warp_sum(fz); en = warp_sum(en);

    __shared__ float sm[4][TPB / 32];
    const int lane = tid & 31, wid = tid >> 5;
    if (lane == 0) { sm[0][wid] = fx; sm[1][wid] = fy; sm[2][wid] = fz; sm[3][wid] = en; }
    __syncthreads();

    if (wid == 0) {
        const int nw = TPB / 32;
        float vfx = (lane < nw) ? sm[0][lane] : 0.f;
        float vfy = (lane < nw) ? sm[1][lane] : 0.f;
        float vfz = (lane < nw) ? sm[2][lane] : 0.f;
        float ven = (lane < nw) ? sm[3][lane] : 0.f;
        vfx = warp_sum(vfx); vfy = warp_sum(vfy); vfz = warp_sum(vfz); ven = warp_sum(ven);
        if (lane == 0) {
            out[1 + 3 * i + 0] = vfx;
            out[1 + 3 * i + 1] = vfy;
            out[1 + 3 * i + 2] = vfz;
            g_epart[i] = ven;
        }
    }

    // ---- last-block deterministic energy reduction ----
    __shared__ int amLast;
    if (tid == 0) {
        __threadfence();
        amLast = (atomicAdd(&g_done, 1u) == (unsigned)(gridDim.x - 1));
    }
    __syncthreads();

    if (amLast) {
        double s = 0.0;
        #pragma unroll
        for (int k = tid; k < NATOMS; k += TPB) s += (double)g_epart[k];

        __shared__ double sd[TPB];
        sd[tid] = s;
        __syncthreads();
        #pragma unroll
        for (int o = TPB / 2; o > 0; o >>= 1) {
            if (tid < o) sd[tid] += sd[tid + o];
            __syncthreads();
        }
        if (tid == 0) {
            out[0] = (float)sd[0];
            g_done = 0;   // reset for next graph replay
        }
    }
}

extern "C" void kernel_launch(void* const* d_in, const int* in_sizes, int n_in,
                              void* d_out, int out_size)
{
    const float* coords = (const float*)d_in[0];
    // d_in[1] = q (computed-but-unused upstream; faithfully ignored)
    const float* A   = (const float*)d_in[2];
    const float* C   = (const float*)d_in[3];
    const float* D   = (const float*)d_in[4];
    const float* RHO = (const float*)d_in[5];
    const float* SIG = (const float*)d_in[6];
    float* out = (float*)d_out;

    bmh_pair_kernel<<<NATOMS, TPB>>>(coords, A, C, D, RHO, SIG, out);
}